// round 12
// baseline (speedup 1.0000x reference)
#include <cuda_runtime.h>
#include <cstdint>
#include <math.h>

// ---- static problem config ----
#define B_        1024
#define C_        64
#define H_        32
#define V_        4096
#define SN_       10
#define FH_ELEMS  2097152      // B*C*H
#define NMAX      32768        // B * max(ph)
#define NSPLIT    32
#define VCHUNK    128          // NSPLIT*VCHUNK == V_

__device__ __constant__ int c_vpatch[SN_] = {1,2,3,4,6,9,13,18,24,32};

// ---- device scratch (no allocations allowed) ----
__device__ float g_frest [FH_ELEMS];
__device__ float g_restNC[NMAX * C_];
__device__ float g_mdown [9 * 32 * 32];
__device__ float g_mup   [9 * 32 * 32];
__device__ float g_esq   [V_];            // full |e|^2 (matches reference e_sq)
__device__ float g_pscore[NMAX * NSPLIT];
__device__ int   g_pidx  [NMAX * NSPLIT];
__device__ int   g_idx   [NMAX];
__device__ float g_bsum  [SN_ * 2 * B_];

// torch bicubic kernel, a = -0.75 (double, matches numpy reference)
__device__ __forceinline__ double dcubic(double x) {
    const double a = -0.75;
    x = fabs(x);
    if (x <= 1.0) return ((a + 2.0) * x - (a + 3.0)) * x * x + 1.0;
    if (x <  2.0) return a * (((x - 5.0) * x + 8.0) * x - 4.0);
    return 0.0;
}

// ---- K0a: init f_rest = f, f_hat(out) = 0 ----
__global__ void k_init(const float* __restrict__ f, float* __restrict__ out) {
    int i = blockIdx.x * 256 + threadIdx.x;
    if (i < FH_ELEMS) { g_frest[i] = f[i]; out[i] = 0.0f; }
}

// ---- K0b: resize matrices (down: align_corners=True, up: align_corners=False) ----
__global__ void k_mats() {
    int t = threadIdx.x;
    if (t >= 576) return;
    int kind = t / 288;       // 0 = down, 1 = up
    int r = t % 288;
    int si = r / 32;          // 0..8 (last scale has no resize)
    int j  = r % 32;
    int ph = c_vpatch[si];
    double w[32];
    #pragma unroll
    for (int i = 0; i < 32; i++) w[i] = 0.0;
    if (kind == 0) {
        // down row p=j: 32 -> ph, align_corners=True
        if (j < ph) {
            double src = (ph == 1) ? 0.0 : (double)j * 31.0 / (double)(ph - 1);
            int fl = (int)floor(src); double tt = src - (double)fl;
            for (int k = -1; k < 3; k++) {
                int ii = fl + k; ii = ii < 0 ? 0 : (ii > 31 ? 31 : ii);
                w[ii] += dcubic((double)k - tt);
            }
        }
        for (int i = 0; i < 32; i++) g_mdown[(si * 32 + j) * 32 + i] = (float)w[i];
    } else {
        // up row o=j: ph -> 32, align_corners=False
        double src = ((double)j + 0.5) * (double)ph / 32.0 - 0.5;
        int fl = (int)floor(src); double tt = src - (double)fl;
        for (int k = -1; k < 3; k++) {
            int ii = fl + k; ii = ii < 0 ? 0 : (ii > ph - 1 ? ph - 1 : ii);
            w[ii] += dcubic((double)k - tt);
        }
        for (int i = 0; i < 32; i++) g_mup[(si * 32 + j) * 32 + i] = (float)w[i];
    }
}

// ---- K0c: full |e|^2 per code ----
__global__ void k_esq(const float* __restrict__ emb) {
    int v = blockIdx.x * 256 + threadIdx.x;
    if (v >= V_) return;
    const float4* e = (const float4*)(emb + v * C_);
    float s = 0.0f;
    #pragma unroll
    for (int k = 0; k < 16; k++) {
        float4 q = e[k];
        s += q.x * q.x + q.y * q.y + q.z * q.z + q.w * q.w;
    }
    g_esq[v] = s;
}

// ---- K1: downsample f_rest (or pass-through f at last scale) into [N, C] rows ----
__global__ void k_down(const float* __restrict__ f, int si, int ph, int N) {
    int t = blockIdx.x * 256 + threadIdx.x;
    if (t >= N * C_) return;
    int c = t & 63, n = t >> 6;
    int b = n / ph, p = n - b * ph;
    float acc;
    if (si == 9) {
        acc = f[(b * C_ + c) * H_ + p];               // rest = f, p == h
    } else {
        const float4* row = (const float4*)(g_frest + (b * C_ + c) * H_);
        const float4* m   = (const float4*)(g_mdown + (si * 32 + p) * 32);
        acc = 0.0f;
        #pragma unroll
        for (int k = 0; k < 8; k++) {
            float4 a = row[k]; float4 mm = m[k];
            acc += a.x * mm.x + a.y * mm.y + a.z * mm.z + a.w * mm.w;
        }
    }
    g_restNC[t] = acc;
}

// packed fp32x2 FMA (sm_100+ only; emits FFMA2 — 2x fp32 MAC rate)
#define FMA2(acc, a, bb) \
    asm("fma.rn.f32x2 %0, %1, %2, %0;" : "+l"(acc) : "l"(a), "l"(bb))

// ---- K2: partial nearest-code search, V split into NSPLIT chunks of VCHUNK ----
// Emulates the reference's rounding sequence exactly:
//   d_v = fl( fl(s + esq_v) - 2*dot_v )      (big-constant fp32 grid!)
// so near-tie argmins resolve identically. Strict-< min keeps first index.
__global__ __launch_bounds__(256) void k_dist(const float* __restrict__ emb, int N) {
    __shared__ __align__(16) float csm[VCHUNK * C_];   // 32 KB code chunk
    __shared__ float esq[VCHUNK];
    int tid = threadIdx.x;
    int vbase = blockIdx.y * VCHUNK;
    {
        const float4* src = (const float4*)(emb + vbase * C_);
        float4* dst = (float4*)csm;
        for (int i = tid; i < VCHUNK * C_ / 4; i += 256) dst[i] = src[i];
        if (tid < VCHUNK) esq[tid] = g_esq[vbase + tid];
    }
    __syncthreads();
    int n = blockIdx.x * 256 + tid;
    if (n >= N) return;

    ulonglong2 xv[16];
    const ulonglong2* xr = (const ulonglong2*)(g_restNC + n * C_);
    #pragma unroll
    for (int k = 0; k < 16; k++) xv[k] = xr[k];

    // s = |x|^2 (accuracy << ulp(s); exact order irrelevant — binade-shift invariant)
    float s = 0.0f;
    {
        const float4* xf = (const float4*)(g_restNC + n * C_);
        #pragma unroll
        for (int k = 0; k < 16; k++) {
            float4 q = xf[k];
            s += q.x * q.x + q.y * q.y + q.z * q.z + q.w * q.w;
        }
    }

    float best = 3.4e38f; int bestv = 0;
    #pragma unroll 2
    for (int v = 0; v < VCHUNK; v++) {
        const ulonglong2* cp = (const ulonglong2*)(csm + v * C_);
        unsigned long long a0 = 0ull, a1 = 0ull;
        #pragma unroll
        for (int k = 0; k < 16; k++) {
            ulonglong2 cv = cp[k];
            FMA2(a0, xv[k].x, cv.x);
            FMA2(a1, xv[k].y, cv.y);
        }
        float l0, h0, l1, h1;
        asm("mov.b64 {%0,%1}, %2;" : "=f"(l0), "=f"(h0) : "l"(a0));
        asm("mov.b64 {%0,%1}, %2;" : "=f"(l1), "=f"(h1) : "l"(a1));
        float dot = __fadd_rn(__fadd_rn(l0, h0), __fadd_rn(l1, h1));
        float t   = __fadd_rn(s, esq[v]);          // fl(s + e_sq_v)  — the coarse grid
        float d   = __fadd_rn(t, -2.0f * dot);     // fl(t - 2*dot)   — 2*dot exact
        if (d < best) { best = d; bestv = vbase + v; }   // strict <: first-index wins
    }
    g_pscore[n * NSPLIT + blockIdx.y] = best;
    g_pidx  [n * NSPLIT + blockIdx.y] = bestv;
}

// ---- K3: combine partial argmin (chunk order ascending -> first-min tie rule) ----
__global__ void k_argred(int N) {
    int n = blockIdx.x * 256 + threadIdx.x;
    if (n >= N) return;
    float best = 3.4e38f; int bi = 0;
    #pragma unroll
    for (int s = 0; s < NSPLIT; s++) {
        float sc = g_pscore[n * NSPLIT + s];
        int   iv = g_pidx  [n * NSPLIT + s];
        if (sc < best) { best = sc; bi = iv; }
    }
    g_idx[n] = bi;
}

// ---- K4: gather + bicubic upsample + 3-tap conv (Phi) + residual/loss/levels ----
// grid = (B, 2): blockIdx.x = batch image, blockIdx.y = co half (32 channels).
// All-static shared memory -> no cudaFuncSetAttribute; launch stays capture-safe.
__global__ __launch_bounds__(256) void k_phi(
    const float* __restrict__ f, const float* __restrict__ emb,
    const float* __restrict__ pw, const float* __restrict__ pb,
    float* __restrict__ out, int si, int ph, int pi)
{
    __shared__ __align__(16) float wsm [3 * 64 * 32];  // w[kh][ci][co_local]
    __shared__ float hsm [64 * 34];                    // h_up with zero halo
    __shared__ __align__(16) float esm [32 * 64];      // gathered code rows
    __shared__ float musm[32 * 32];                    // upsample matrix
    __shared__ float red [256];

    int tid = threadIdx.x, b = blockIdx.x, half = blockIdx.y;
    int co0 = half * 32;

    // stage this half's weights as wsm[kh][ci][co_local]  (kw=1 only; W=1)
    for (int i = tid; i < 3 * 64 * 32; i += 256) {
        int col = i & 31, r = i >> 5, ci = r & 63, kh = r >> 6;
        wsm[i] = pw[((pi * 64 + (co0 + col)) * 64 + ci) * 9 + kh * 3 + 1];
    }
    for (int i = tid; i < ph * 64; i += 256) {
        int p = i >> 6, c = i & 63;
        esm[i] = emb[g_idx[b * ph + p] * 64 + c];
    }
    if (si < 9)
        for (int i = tid; i < 1024; i += 256) musm[i] = g_mup[si * 1024 + i];
    __syncthreads();

    // h_up (with zero halo at o=-1 and o=32); needs ALL ci (both halves compute it)
    for (int u = tid; u < 2048; u += 256) {
        int o = u & 31, c = u >> 5;
        float val;
        if (si == 9) val = esm[o * 64 + c];
        else {
            val = 0.0f;
            for (int p = 0; p < ph; p++) val += musm[o * 32 + p] * esm[p * 64 + c];
        }
        hsm[c * 34 + o + 1] = val;
    }
    if (tid < 64) { hsm[tid * 34] = 0.0f; hsm[tid * 34 + 33] = 0.0f; }
    __syncthreads();

    // conv: warp w handles co_local in [w*4, w*4+4), lane = output row o
    int lane = tid & 31, wrp = tid >> 5;
    int clocal = wrp * 4;
    float acc[4];
    #pragma unroll
    for (int j = 0; j < 4; j++) acc[j] = 0.0f;
    #pragma unroll
    for (int kh = 0; kh < 3; kh++) {
        #pragma unroll 8
        for (int ci = 0; ci < 64; ci++) {
            float h = hsm[ci * 34 + lane + kh];      // input row = lane + kh - 1
            float4 wa = *(const float4*)&wsm[(kh * 64 + ci) * 32 + clocal];
            acc[0] += h * wa.x; acc[1] += h * wa.y; acc[2] += h * wa.z; acc[3] += h * wa.w;
        }
    }

    float local = 0.0f;
    float* lev = out + (FH_ELEMS + 1) + si * FH_ELEMS;
    #pragma unroll
    for (int j = 0; j < 4; j++) {
        int co = co0 + clocal + j;
        float y    = acc[j] + pb[pi * 64 + co];
        float hu   = hsm[co * 34 + lane + 1];
        float hphi = 0.5f * hu + 0.5f * y;           // QRESI = 0.5
        int g = b * 2048 + co * 32 + lane;
        float fh = out[g] + hphi;                    // f_hat accumulator lives in d_out
        out[g] = fh;
        if (si < 9) g_frest[g] -= hphi;
        lev[g] = fh;
        float d = fh - f[g];
        local += d * d;
    }
    // deterministic block reduction
    red[tid] = local; __syncthreads();
    for (int s = 128; s > 0; s >>= 1) {
        if (tid < s) red[tid] += red[tid + s];
        __syncthreads();
    }
    if (tid == 0) g_bsum[(si * 2 + half) * 1024 + b] = red[0];
}

// ---- K5: deterministic final loss ----
__global__ void k_loss(float* __restrict__ out) {
    __shared__ double rd[256];
    int tid = threadIdx.x;
    double s = 0.0;
    for (int i = tid; i < SN_ * 2 * B_; i += 256) s += (double)g_bsum[i];
    rd[tid] = s; __syncthreads();
    for (int st = 128; st > 0; st >>= 1) {
        if (tid < st) rd[tid] += rd[tid + st];
        __syncthreads();
    }
    // loss = sum_si (1+beta)*mean_si / SN = 1.25 * S / (2097152 * 10)
    if (tid == 0) out[FH_ELEMS] = (float)(1.25 * rd[0] / 20971520.0);
}

extern "C" void kernel_launch(void* const* d_in, const int* in_sizes, int n_in,
                              void* d_out, int out_size) {
    const float* f   = (const float*)d_in[0];
    const float* emb = (const float*)d_in[1];
    const float* pw  = (const float*)d_in[2];
    const float* pb  = (const float*)d_in[3];
    float* out = (float*)d_out;
    (void)in_sizes; (void)n_in; (void)out_size;

    const int VP[SN_] = {1, 2, 3, 4, 6, 9, 13, 18, 24, 32};
    // phi index per scale from exact float64 analysis of np.linspace ticks
    // (si=2: half-even rounding makes d1 < d0 -> 1; si=7: d3 < d2 by 1 ulp -> 3)
    const int PI[SN_] = {0, 0, 1, 1, 1, 2, 2, 3, 3, 3};

    k_init<<<(FH_ELEMS + 255) / 256, 256>>>(f, out);
    k_mats<<<1, 576>>>();
    k_esq<<<V_ / 256, 256>>>(emb);

    for (int si = 0; si < SN_; si++) {
        int ph = VP[si];
        int N  = B_ * ph;
        k_down<<<(N * C_ + 255) / 256, 256>>>(f, si, ph, N);
        dim3 gd((N + 255) / 256, NSPLIT);
        k_dist<<<gd, 256>>>(emb, N);
        k_argred<<<(N + 255) / 256, 256>>>(N);
        dim3 gp(B_, 2);
        k_phi<<<gp, 256>>>(f, emb, pw, pb, out, si, ph, PI[si]);
    }
    k_loss<<<1, 256>>>(out);
}

// round 16
// speedup vs baseline: 1.4634x; 1.4634x over previous
#include <cuda_runtime.h>
#include <cuda_bf16.h>
#include <cstdint>
#include <math.h>

// ---- static problem config ----
#define B_        1024
#define C_        64
#define H_        32
#define V_        4096
#define SN_       10
#define FH_ELEMS  2097152      // B*C*H
#define NMAX      32768        // B * max(ph)
#define NSPLITS   4            // V split across blockIdx.y in k_screen
#define VSPLIT    1024         // codes per split
#define NCHUNK    8            // 128-code chunks per split
#define TOTCHUNK  32           // total 128-code chunks (NSPLITS*NCHUNK)

__device__ __constant__ int c_vpatch[SN_] = {1,2,3,4,6,9,13,18,24,32};

// ---- device scratch (no allocations allowed) ----
__device__ float g_frest [FH_ELEMS];
__device__ float g_restNC[NMAX * C_];
__device__ float g_mdown [9 * 32 * 32];
__device__ float g_mup   [9 * 32 * 32];
__device__ float g_esq   [V_];
__device__ __nv_bfloat16 g_embh[V_ * C_];          // bf16 codebook
__device__ unsigned int g_emaxbits;                // max ||e||^2 bits (zero-init)
__device__ float g_cmin [TOTCHUNK * NMAX];         // per (chunk,row) bf16-screen min d
__device__ int   g_wcnt [TOTCHUNK];                // worklist counts
__device__ int   g_wl   [TOTCHUNK * NMAX];         // worklist rows per chunk
__device__ unsigned long long g_best[NMAX];        // packed (mono(d) << 32) | code
__device__ float g_bsum [SN_ * 2 * B_];

// ======================= helpers =======================
__device__ __forceinline__ uint32_t smem_u32(const void* p) {
    uint32_t a;
    asm("{ .reg .u64 t; cvta.to.shared.u64 t, %1; cvt.u32.u64 %0, t; }"
        : "=r"(a) : "l"(p));
    return a;
}
__device__ __forceinline__ uint32_t pack_bf16x2(float lo, float hi) {
    uint32_t l = __bfloat16_as_ushort(__float2bfloat16_rn(lo));
    uint32_t h = __bfloat16_as_ushort(__float2bfloat16_rn(hi));
    return (h << 16) | l;
}
#define SW128(b)  ((b) ^ (((b) >> 3) & 0x70))

__device__ __forceinline__ void mma16816(float* d, const uint32_t* a,
                                         uint32_t b0, uint32_t b1) {
    asm volatile("mma.sync.aligned.m16n8k16.row.col.f32.bf16.bf16.f32 "
        "{%0,%1,%2,%3}, {%4,%5,%6,%7}, {%8,%9}, {%0,%1,%2,%3};"
        : "+f"(d[0]), "+f"(d[1]), "+f"(d[2]), "+f"(d[3])
        : "r"(a[0]), "r"(a[1]), "r"(a[2]), "r"(a[3]), "r"(b0), "r"(b1));
}
#define LDMATRIX_X4(r0, r1, r2, r3, addr) \
    asm volatile("ldmatrix.sync.aligned.m8n8.x4.shared.b16 {%0,%1,%2,%3}, [%4];" \
        : "=r"(r0), "=r"(r1), "=r"(r2), "=r"(r3) : "r"(addr))
#define LDMATRIX_X2(r0, r1, addr) \
    asm volatile("ldmatrix.sync.aligned.m8n8.x2.shared.b16 {%0,%1}, [%2];" \
        : "=r"(r0), "=r"(r1) : "r"(addr))

// torch bicubic kernel, a = -0.75
__device__ __forceinline__ double dcubic(double x) {
    const double a = -0.75;
    x = fabs(x);
    if (x <= 1.0) return ((a + 2.0) * x - (a + 3.0)) * x * x + 1.0;
    if (x <  2.0) return a * (((x - 5.0) * x + 8.0) * x - 4.0);
    return 0.0;
}

// ---- K0a: init f_rest = f, f_hat(out) = 0 ----
__global__ void k_init(const float* __restrict__ f, float* __restrict__ out) {
    int i = blockIdx.x * 256 + threadIdx.x;
    if (i < FH_ELEMS) { g_frest[i] = f[i]; out[i] = 0.0f; }
}

// ---- K0b: resize matrices (down: align_corners=True, up: align_corners=False) ----
__global__ void k_mats() {
    int t = threadIdx.x;
    if (t >= 576) return;
    int kind = t / 288;
    int r = t % 288;
    int si = r / 32;
    int j  = r % 32;
    int ph = c_vpatch[si];
    double w[32];
    #pragma unroll
    for (int i = 0; i < 32; i++) w[i] = 0.0;
    if (kind == 0) {
        if (j < ph) {
            double src = (ph == 1) ? 0.0 : (double)j * 31.0 / (double)(ph - 1);
            int fl = (int)floor(src); double tt = src - (double)fl;
            for (int k = -1; k < 3; k++) {
                int ii = fl + k; ii = ii < 0 ? 0 : (ii > 31 ? 31 : ii);
                w[ii] += dcubic((double)k - tt);
            }
        }
        for (int i = 0; i < 32; i++) g_mdown[(si * 32 + j) * 32 + i] = (float)w[i];
    } else {
        double src = ((double)j + 0.5) * (double)ph / 32.0 - 0.5;
        int fl = (int)floor(src); double tt = src - (double)fl;
        for (int k = -1; k < 3; k++) {
            int ii = fl + k; ii = ii < 0 ? 0 : (ii > ph - 1 ? ph - 1 : ii);
            w[ii] += dcubic((double)k - tt);
        }
        for (int i = 0; i < 32; i++) g_mup[(si * 32 + j) * 32 + i] = (float)w[i];
    }
}

// ---- K0c: |e|^2, bf16 codebook, max||e||^2 ----
__global__ void k_prep(const float* __restrict__ emb) {
    int v = blockIdx.x * 256 + threadIdx.x;
    if (v >= V_) return;
    const float4* e = (const float4*)(emb + v * C_);
    uint32_t* dst = (uint32_t*)(g_embh + v * C_);
    float s = 0.0f;
    #pragma unroll
    for (int k = 0; k < 16; k++) {
        float4 q = e[k];
        s += q.x * q.x + q.y * q.y + q.z * q.z + q.w * q.w;
        dst[2 * k]     = pack_bf16x2(q.x, q.y);
        dst[2 * k + 1] = pack_bf16x2(q.z, q.w);
    }
    g_esq[v] = s;
    atomicMax(&g_emaxbits, __float_as_uint(s));   // s >= 0 -> bit-monotone
}

// ---- K1: downsample f_rest (or pass f at last scale) into [N, C] rows ----
__global__ void k_down(const float* __restrict__ f, int si, int ph, int N) {
    int t = blockIdx.x * 256 + threadIdx.x;
    if (t >= N * C_) return;
    int c = t & 63, n = t >> 6;
    int b = n / ph, p = n - b * ph;
    float acc;
    if (si == 9) {
        acc = f[(b * C_ + c) * H_ + p];
    } else {
        const float4* row = (const float4*)(g_frest + (b * C_ + c) * H_);
        const float4* m   = (const float4*)(g_mdown + (si * 32 + p) * 32);
        acc = 0.0f;
        #pragma unroll
        for (int k = 0; k < 8; k++) {
            float4 a = row[k]; float4 mm = m[k];
            acc += a.x * mm.x + a.y * mm.y + a.z * mm.z + a.w * mm.w;
        }
    }
    g_restNC[t] = acc;
}

// ---- zero worklist counters ----
__global__ void k_zero() {
    if (threadIdx.x < TOTCHUNK) g_wcnt[threadIdx.x] = 0;
}

// ---- K2: HMMA bf16 screening GEMM -> per-(row, 128-code-chunk) min d ----
// grid = (N/128, NSPLITS), block = 128 (4 warps x 32 rows each).
__global__ __launch_bounds__(128) void k_screen() {
    __shared__ __align__(1024) char Asm[128 * 128];   // 128 rows x 64 bf16 (SW128)
    __shared__ __align__(1024) char Bsm[128 * 128];   // 128 codes x 64 bf16 (SW128)
    __shared__ float esqs[128];
    __shared__ float ssm [128];

    int tid  = threadIdx.x;
    int lane = tid & 31, wid = tid >> 5;
    int rowbase = blockIdx.x * 128;
    uint32_t sb_a = smem_u32(Asm), sb_b = smem_u32(Bsm);

    // A: thread tid converts its row to bf16 (SW128) and computes s = |x|^2
    {
        float s = 0.0f;
        const float4* xr = (const float4*)(g_restNC + (size_t)(rowbase + tid) * C_);
        #pragma unroll
        for (int i = 0; i < 8; i++) {
            float4 a = xr[2 * i], b = xr[2 * i + 1];
            s += a.x * a.x + a.y * a.y + a.z * a.z + a.w * a.w;
            s += b.x * b.x + b.y * b.y + b.z * b.z + b.w * b.w;
            uint32_t p0 = pack_bf16x2(a.x, a.y);
            uint32_t p1 = pack_bf16x2(a.z, a.w);
            uint32_t p2 = pack_bf16x2(b.x, b.y);
            uint32_t p3 = pack_bf16x2(b.z, b.w);
            uint32_t off = SW128((uint32_t)(tid * 128 + i * 16));
            asm volatile("st.shared.v4.b32 [%0], {%1,%2,%3,%4};"
                :: "r"(sb_a + off), "r"(p0), "r"(p1), "r"(p2), "r"(p3) : "memory");
        }
        ssm[tid] = s;
    }
    __syncthreads();

    // preload A fragments: 2 m-tiles x 4 k-steps x 4 regs (constant across chunks)
    uint32_t afr[2][4][4];
    int slab = wid * 32;
    #pragma unroll
    for (int mt = 0; mt < 2; mt++)
        #pragma unroll
        for (int kk = 0; kk < 4; kk++) {
            int r    = slab + mt * 16 + ((lane >> 3) & 1) * 8 + (lane & 7);
            int colb = kk * 32 + ((lane >> 4) & 1) * 16;
            uint32_t addr = sb_a + SW128((uint32_t)(r * 128 + colb));
            LDMATRIX_X4(afr[mt][kk][0], afr[mt][kk][1], afr[mt][kk][2], afr[mt][kk][3], addr);
        }

    int vbase0 = blockIdx.y * VSPLIT;
    for (int cc = 0; cc < NCHUNK; cc++) {
        int v0 = vbase0 + cc * 128;
        __syncthreads();   // prior chunk's readers done before Bsm overwrite
        // load B chunk (bf16 codebook rows are 128B): coalesced float4 copy
        {
            const float4* src = (const float4*)(g_embh + (size_t)v0 * C_);
            for (int i = tid; i < 1024; i += 128) {
                float4 d = src[i];
                uint32_t off = SW128((uint32_t)(i * 16));
                asm volatile("st.shared.v4.b32 [%0], {%1,%2,%3,%4};"
                    :: "r"(sb_b + off), "r"(__float_as_uint(d.x)), "r"(__float_as_uint(d.y)),
                       "r"(__float_as_uint(d.z)), "r"(__float_as_uint(d.w)) : "memory");
            }
            esqs[tid] = g_esq[v0 + tid];
        }
        __syncthreads();

        float vmin[4] = {3.4e38f, 3.4e38f, 3.4e38f, 3.4e38f};
        #pragma unroll
        for (int nt = 0; nt < 16; nt++) {
            int n0 = nt * 8;
            float dd[2][4] = {{0.f,0.f,0.f,0.f},{0.f,0.f,0.f,0.f}};
            #pragma unroll
            for (int kk = 0; kk < 4; kk++) {
                int br    = n0 + (lane & 7);
                int bcolb = kk * 32 + ((lane >> 3) & 1) * 16;
                uint32_t baddr = sb_b + SW128((uint32_t)(br * 128 + bcolb));
                uint32_t b0, b1;
                LDMATRIX_X2(b0, b1, baddr);
                mma16816(dd[0], afr[0][kk], b0, b1);
                mma16816(dd[1], afr[1][kk], b0, b1);
            }
            int c0 = n0 + (lane & 3) * 2;
            float e0 = esqs[c0], e1 = esqs[c0 + 1];
            #pragma unroll
            for (int mt = 0; mt < 2; mt++) {
                float q0 = fminf(e0 - 2.0f * dd[mt][0], e1 - 2.0f * dd[mt][1]);
                float q1 = fminf(e0 - 2.0f * dd[mt][2], e1 - 2.0f * dd[mt][3]);
                vmin[mt * 2 + 0] = fminf(vmin[mt * 2 + 0], q0);
                vmin[mt * 2 + 1] = fminf(vmin[mt * 2 + 1], q1);
            }
        }
        // reduce over the 4 lanes sharing each row (lane>>2 groups)
        #pragma unroll
        for (int x = 1; x <= 2; x <<= 1)
            #pragma unroll
            for (int j = 0; j < 4; j++)
                vmin[j] = fminf(vmin[j], __shfl_xor_sync(0xffffffffu, vmin[j], x));
        if ((lane & 3) == 0) {
            int q = lane >> 2;
            int ch = blockIdx.y * NCHUNK + cc;
            #pragma unroll
            for (int j = 0; j < 4; j++) {
                int rl = slab + q + (j & 1) * 8 + (j >> 1) * 16;
                g_cmin[(size_t)ch * NMAX + rowbase + rl] = ssm[rl] + vmin[j];
            }
        }
    }
}

// ---- K3: per-row threshold + worklist build + best-key init ----
__global__ void k_qualify(int N) {
    int n = blockIdx.x * 256 + threadIdx.x;
    if (n >= N) return;
    float cm[TOTCHUNK];
    float gmin = 3.4e38f;
    #pragma unroll
    for (int ch = 0; ch < TOTCHUNK; ch++) {
        float c = g_cmin[(size_t)ch * NMAX + n];
        cm[ch] = c;
        gmin = fminf(gmin, c);
    }
    float s = 0.0f;
    {
        const float4* xr = (const float4*)(g_restNC + (size_t)n * C_);
        #pragma unroll
        for (int k = 0; k < 16; k++) {
            float4 q = xr[k];
            s += q.x * q.x + q.y * q.y + q.z * q.z + q.w * q.w;
        }
    }
    float emax2 = __uint_as_float(g_emaxbits);
    float thr = gmin + 0.016f * sqrtf(s * emax2) + 1e-3f;   // >= 2x bf16 dot bound + slack
    g_best[n] = 0xFFFFFFFFFFFFFFFFull;
    #pragma unroll
    for (int ch = 0; ch < TOTCHUNK; ch++) {
        if (cm[ch] <= thr) {
            int p = atomicAdd(&g_wcnt[ch], 1);
            g_wl[(size_t)ch * NMAX + p] = n;
        }
    }
}

// ---- K4: exact rescore of qualifying (row, chunk) pairs ----
// grid = (N/128, TOTCHUNK). Chunk codes staged in smem; reference rounding grid;
// packed atomicMin key = (mono(d) << 32) | v  ->  min d, tie -> min v (first index).
__global__ __launch_bounds__(128) void k_rescan(const float* __restrict__ emb) {
    __shared__ __align__(16) float cs[128 * 64];
    __shared__ float es[128];
    int ch = blockIdx.y;
    int cnt = g_wcnt[ch];
    if (blockIdx.x * 128 >= cnt) return;
    int tid = threadIdx.x;
    int v0 = ch * 128;
    {
        const float4* src = (const float4*)(emb + (size_t)v0 * C_);
        float4* dst = (float4*)cs;
        for (int i = tid; i < 128 * 16; i += 128) dst[i] = src[i];
        es[tid] = g_esq[v0 + tid];
    }
    __syncthreads();
    int idx = blockIdx.x * 128 + tid;
    if (idx >= cnt) return;
    int n = g_wl[(size_t)ch * NMAX + idx];

    float x[64];
    float s = 0.0f;
    {
        const float4* xr = (const float4*)(g_restNC + (size_t)n * C_);
        #pragma unroll
        for (int k = 0; k < 16; k++) {
            float4 q = xr[k];
            x[4 * k] = q.x; x[4 * k + 1] = q.y; x[4 * k + 2] = q.z; x[4 * k + 3] = q.w;
            s += q.x * q.x + q.y * q.y + q.z * q.z + q.w * q.w;
        }
    }
    float best = 3.4e38f; int bi = v0;
    for (int v = 0; v < 128; v++) {
        const float* e = cs + v * 64;
        float a0 = 0.f, a1 = 0.f, a2 = 0.f, a3 = 0.f;
        #pragma unroll
        for (int k = 0; k < 16; k++) {
            a0 = fmaf(x[4 * k],     e[4 * k],     a0);
            a1 = fmaf(x[4 * k + 1], e[4 * k + 1], a1);
            a2 = fmaf(x[4 * k + 2], e[4 * k + 2], a2);
            a3 = fmaf(x[4 * k + 3], e[4 * k + 3], a3);
        }
        float dot = __fadd_rn(__fadd_rn(a0, a1), __fadd_rn(a2, a3));
        float t   = __fadd_rn(s, es[v]);           // coarse reference grid
        float d   = __fadd_rn(t, -2.0f * dot);
        if (d < best) { best = d; bi = v0 + v; }   // strict <: first-index in chunk
    }
    uint32_t u = __float_as_uint(best);
    uint32_t mono = (u & 0x80000000u) ? ~u : (u | 0x80000000u);
    unsigned long long key = ((unsigned long long)mono << 32) | (uint32_t)bi;
    atomicMin(&g_best[n], key);
}

// ---- K5: gather + bicubic upsample + 3-tap conv (Phi) + residual/loss/levels ----
__global__ __launch_bounds__(256) void k_phi(
    const float* __restrict__ f, const float* __restrict__ emb,
    const float* __restrict__ pw, const float* __restrict__ pb,
    float* __restrict__ out, int si, int ph, int pi)
{
    __shared__ __align__(16) float wsm [3 * 64 * 32];
    __shared__ float hsm [64 * 34];
    __shared__ __align__(16) float esm [32 * 64];
    __shared__ float musm[32 * 32];
    __shared__ float red [256];

    int tid = threadIdx.x, b = blockIdx.x, half = blockIdx.y;
    int co0 = half * 32;

    for (int i = tid; i < 3 * 64 * 32; i += 256) {
        int col = i & 31, r = i >> 5, ci = r & 63, kh = r >> 6;
        wsm[i] = pw[((pi * 64 + (co0 + col)) * 64 + ci) * 9 + kh * 3 + 1];
    }
    for (int i = tid; i < ph * 64; i += 256) {
        int p = i >> 6, c = i & 63;
        int code = (int)(g_best[b * ph + p] & 0xFFFFFFFFull);
        esm[i] = emb[code * 64 + c];
    }
    if (si < 9)
        for (int i = tid; i < 1024; i += 256) musm[i] = g_mup[si * 1024 + i];
    __syncthreads();

    for (int u = tid; u < 2048; u += 256) {
        int o = u & 31, c = u >> 5;
        float val;
        if (si == 9) val = esm[o * 64 + c];
        else {
            val = 0.0f;
            for (int p = 0; p < ph; p++) val += musm[o * 32 + p] * esm[p * 64 + c];
        }
        hsm[c * 34 + o + 1] = val;
    }
    if (tid < 64) { hsm[tid * 34] = 0.0f; hsm[tid * 34 + 33] = 0.0f; }
    __syncthreads();

    int lane = tid & 31, wrp = tid >> 5;
    int clocal = wrp * 4;
    float acc[4];
    #pragma unroll
    for (int j = 0; j < 4; j++) acc[j] = 0.0f;
    #pragma unroll
    for (int kh = 0; kh < 3; kh++) {
        #pragma unroll 8
        for (int ci = 0; ci < 64; ci++) {
            float h = hsm[ci * 34 + lane + kh];
            float4 wa = *(const float4*)&wsm[(kh * 64 + ci) * 32 + clocal];
            acc[0] += h * wa.x; acc[1] += h * wa.y; acc[2] += h * wa.z; acc[3] += h * wa.w;
        }
    }

    float local = 0.0f;
    float* lev = out + (FH_ELEMS + 1) + si * FH_ELEMS;
    #pragma unroll
    for (int j = 0; j < 4; j++) {
        int co = co0 + clocal + j;
        float y    = acc[j] + pb[pi * 64 + co];
        float hu   = hsm[co * 34 + lane + 1];
        float hphi = 0.5f * hu + 0.5f * y;
        int g = b * 2048 + co * 32 + lane;
        float fh = out[g] + hphi;
        out[g] = fh;
        if (si < 9) g_frest[g] -= hphi;
        lev[g] = fh;
        float d = fh - f[g];
        local += d * d;
    }
    red[tid] = local; __syncthreads();
    for (int st = 128; st > 0; st >>= 1) {
        if (tid < st) red[tid] += red[tid + st];
        __syncthreads();
    }
    if (tid == 0) g_bsum[(si * 2 + half) * 1024 + b] = red[0];
}

// ---- K6: deterministic final loss ----
__global__ void k_loss(float* __restrict__ out) {
    __shared__ double rd[256];
    int tid = threadIdx.x;
    double s = 0.0;
    for (int i = tid; i < SN_ * 2 * B_; i += 256) s += (double)g_bsum[i];
    rd[tid] = s; __syncthreads();
    for (int st = 128; st > 0; st >>= 1) {
        if (tid < st) rd[tid] += rd[tid + st];
        __syncthreads();
    }
    if (tid == 0) out[FH_ELEMS] = (float)(1.25 * rd[0] / 20971520.0);
}

extern "C" void kernel_launch(void* const* d_in, const int* in_sizes, int n_in,
                              void* d_out, int out_size) {
    const float* f   = (const float*)d_in[0];
    const float* emb = (const float*)d_in[1];
    const float* pw  = (const float*)d_in[2];
    const float* pb  = (const float*)d_in[3];
    float* out = (float*)d_out;
    (void)in_sizes; (void)n_in; (void)out_size;

    const int VP[SN_] = {1, 2, 3, 4, 6, 9, 13, 18, 24, 32};
    // phi index per scale (exact float64 analysis of np.linspace ticks)
    const int PI[SN_] = {0, 0, 1, 1, 1, 2, 2, 3, 3, 3};

    k_init<<<(FH_ELEMS + 255) / 256, 256>>>(f, out);
    k_mats<<<1, 576>>>();
    k_prep<<<V_ / 256, 256>>>(emb);

    for (int si = 0; si < SN_; si++) {
        int ph = VP[si];
        int N  = B_ * ph;
        k_down<<<(N * C_ + 255) / 256, 256>>>(f, si, ph, N);
        k_zero<<<1, 32>>>();
        dim3 gs(N / 128, NSPLITS);
        k_screen<<<gs, 128>>>();
        k_qualify<<<(N + 255) / 256, 256>>>(N);
        dim3 gr(N / 128, TOTCHUNK);
        k_rescan<<<gr, 128>>>(emb);
        dim3 gp(B_, 2);
        k_phi<<<gp, 256>>>(f, emb, pw, pb, out, si, ph, PI[si]);
    }
    k_loss<<<1, 256>>>(out);
}